// round 12
// baseline (speedup 1.0000x reference)
#include <cuda_runtime.h>
#include <math.h>

#define Nn   100000
#define Ee   1600000
#define Fin  128
#define Hh   64
#define Cc   40
#define NB_SCAN ((Nn + 1023) / 1024)
#define NB_G1  ((Nn + 255) / 256)       // gemm1 blocks in the fused kernel
#define NB_HIST ((Ee + 255) / 256)      // hist blocks in the fused kernel
#define FLAGBIT (1 << 30)

// ---------------- scratch (static device globals; no runtime alloc) -------
__device__ __align__(256) float g_bufA[Nn * Hh];     // final h for gemm2
__device__ __align__(256) float g_xnA [Nn * Hh];
__device__ __align__(256) float g_xnB [Nn * Hh];
__device__ float g_nrmA[Nn];
__device__ float g_nrmB[Nn];
__device__ int   g_deg [Nn];          // zero at module load; re-zeroed each call by k_scan
__device__ int   g_rowptr[Nn + 1];
__device__ int   g_rank[Ee];
__device__ int   g_col [Ee];
__device__ int   g_bsums[NB_SCAN];

// ---------------- helpers --------------------------------------------------
__device__ __forceinline__ float warp_sum(float v) {
    #pragma unroll
    for (int o = 16; o > 0; o >>= 1) v += __shfl_xor_sync(0xffffffffu, v, o);
    return v;
}
__device__ __forceinline__ float warp_max(float v) {
    #pragma unroll
    for (int o = 16; o > 0; o >>= 1) v = fmaxf(v, __shfl_xor_sync(0xffffffffu, v, o));
    return v;
}
__device__ __forceinline__ float red8(float v, unsigned m) {
    v += __shfl_xor_sync(m, v, 1);
    v += __shfl_xor_sync(m, v, 2);
    v += __shfl_xor_sync(m, v, 4);
    return v;
}
__device__ __forceinline__ float dot8(float4 a0, float4 a1, float4 b0, float4 b1) {
    return a0.x * b0.x + a0.y * b0.y + a0.z * b0.z + a0.w * b0.w
         + a1.x * b1.x + a1.y * b1.y + a1.z * b1.z + a1.w * b1.w;
}

#define FFMA2(d, a, b, c) \
    asm("fma.rn.f32x2 %0, %1, %2, %3;" : "=l"(d) : "l"(a), "l"(b), "l"(c))

union F2U { float2 f; unsigned long long u; };
__device__ __forceinline__ unsigned long long pack_dup(float v) {
    unsigned long long r;
    asm("mov.b64 %0, {%1, %1};" : "=l"(r) : "f"(v));
    return r;
}

// cp.async 16B (L1-bypass) + group ops
__device__ __forceinline__ void cp16(unsigned s, const void* g) {
    asm volatile("cp.async.cg.shared.global [%0], [%1], 16;" :: "r"(s), "l"(g));
}
#define CP_COMMIT() asm volatile("cp.async.commit_group;" ::: "memory")
#define CP_WAIT1()  asm volatile("cp.async.wait_group 1;" ::: "memory")
#define CP_WAIT0()  asm volatile("cp.async.wait_group 0;" ::: "memory")

__device__ __forceinline__ float4 lds128(unsigned a) {
    float4 v;
    asm volatile("ld.shared.v4.f32 {%0,%1,%2,%3}, [%4];"
                 : "=f"(v.x), "=f"(v.y), "=f"(v.z), "=f"(v.w) : "r"(a));
    return v;
}

// ---------------- fused GEMM1 + hist ---------------------------------------
__global__ void __launch_bounds__(256, 2)
k_gemm1_hist(const float* __restrict__ x, const float* __restrict__ W1,
             const float* __restrict__ b1, const int* __restrict__ edge_index) {
    __shared__ __align__(16) float Ws[Fin * Hh];   // 32 KB
    __shared__ __align__(16) float As[16][260];    // 16.25 KB, padded stride
    int t = threadIdx.x;                  // 256 threads

    if (blockIdx.x >= NB_G1) {
        // ---- hist part ----
        int bb = blockIdx.x - NB_G1;
        if (bb == 0 && t < NB_SCAN) g_bsums[t] = 0;
        int e = bb * 256 + t;
        if (e < Ee) {
            int r = atomicAdd(&g_deg[edge_index[Ee + e]], 1);
            g_rank[e] = r;
        }
        return;
    }

    // ---- gemm1 part ----
    int row0 = blockIdx.x * 256;
    for (int i = t; i < Fin * Hh; i += 256) Ws[i] = W1[i];

    int tx = t & 7;    // col groups tx*4 and 32+tx*4
    int ty = t >> 3;   // row groups ty*4 and 128+ty*4
    unsigned long long acc[8][4] = {};    // [row][colpair], 64 regs

    for (int k0 = 0; k0 < Fin; k0 += 16) {
        __syncthreads();
        {
            int c = t & 15;
            int r0 = t >> 4;
            #pragma unroll
            for (int i = 0; i < 16; i++) {
                int rr = r0 + i * 16;
                int grow = row0 + rr;
                As[c][rr] = (grow < Nn) ? x[grow * Fin + k0 + c] : 0.f;
            }
        }
        __syncthreads();
        #pragma unroll
        for (int kk = 0; kk < 16; kk++) {
            float4 af0 = *(const float4*)&As[kk][ty * 4];
            float4 af1 = *(const float4*)&As[kk][128 + ty * 4];
            ulonglong2 w0 = *(const ulonglong2*)&Ws[(k0 + kk) * Hh + tx * 4];
            ulonglong2 w1 = *(const ulonglong2*)&Ws[(k0 + kk) * Hh + 32 + tx * 4];
            unsigned long long ad[8];
            ad[0] = pack_dup(af0.x); ad[1] = pack_dup(af0.y);
            ad[2] = pack_dup(af0.z); ad[3] = pack_dup(af0.w);
            ad[4] = pack_dup(af1.x); ad[5] = pack_dup(af1.y);
            ad[6] = pack_dup(af1.z); ad[7] = pack_dup(af1.w);
            #pragma unroll
            for (int r = 0; r < 8; r++) {
                FFMA2(acc[r][0], ad[r], w0.x, acc[r][0]);
                FFMA2(acc[r][1], ad[r], w0.y, acc[r][1]);
                FFMA2(acc[r][2], ad[r], w1.x, acc[r][2]);
                FFMA2(acc[r][3], ad[r], w1.y, acc[r][3]);
            }
        }
    }

    float4 bb0 = *(const float4*)&b1[tx * 4];
    float4 bb1 = *(const float4*)&b1[32 + tx * 4];
    unsigned qm = 0xffu << (t & 24);
    #pragma unroll
    for (int r = 0; r < 8; r++) {
        int grow = row0 + ((r < 4) ? (ty * 4 + r) : (128 + ty * 4 + r - 4));
        F2U u0, u1, u2, u3;
        u0.u = acc[r][0]; u1.u = acc[r][1]; u2.u = acc[r][2]; u3.u = acc[r][3];
        float4 o0, o1;
        o0.x = fmaxf(u0.f.x + bb0.x, 0.f);
        o0.y = fmaxf(u0.f.y + bb0.y, 0.f);
        o0.z = fmaxf(u1.f.x + bb0.z, 0.f);
        o0.w = fmaxf(u1.f.y + bb0.w, 0.f);
        o1.x = fmaxf(u2.f.x + bb1.x, 0.f);
        o1.y = fmaxf(u2.f.y + bb1.y, 0.f);
        o1.z = fmaxf(u3.f.x + bb1.z, 0.f);
        o1.w = fmaxf(u3.f.y + bb1.w, 0.f);
        float ss = red8(dot8(o0, o1, o0, o1), qm);
        float nrm = sqrtf(ss);
        float inv = 1.f / fmaxf(nrm, 1e-12f);
        if (grow < Nn) {
            float4 x0, x1;
            x0.x = o0.x * inv; x0.y = o0.y * inv; x0.z = o0.z * inv; x0.w = o0.w * inv;
            x1.x = o1.x * inv; x1.y = o1.y * inv; x1.z = o1.z * inv; x1.w = o1.w * inv;
            *(float4*)&g_xnA[grow * Hh + tx * 4]      = x0;
            *(float4*)&g_xnA[grow * Hh + 32 + tx * 4] = x1;
            if (tx == 0) g_nrmA[grow] = nrm;
        }
    }
}

// ---------------- single-kernel scan (decoupled lookback) ------------------
__global__ void k_scan() {
    __shared__ int s[1024];
    __shared__ int sb[128];
    int t = threadIdx.x;
    int b = blockIdx.x;
    int idx = b * 1024 + t;
    int v = (idx < Nn) ? g_deg[idx] : 0;
    s[t] = v;
    __syncthreads();
    #pragma unroll
    for (int off = 1; off < 1024; off <<= 1) {
        int x = (t >= off) ? s[t - off] : 0;
        __syncthreads();
        s[t] += x;
        __syncthreads();
    }
    int incl = s[t];
    if (t == 1023) atomicExch(&g_bsums[b], incl | FLAGBIT);

    int myv = 0;
    if (t < b) {
        int x;
        do { x = atomicAdd(&g_bsums[t], 0); } while (!(x & FLAGBIT));
        myv = x & (FLAGBIT - 1);
    }
    if (t < 128) sb[t] = (t < b) ? myv : 0;
    __syncthreads();
    if (t < 64) sb[t] += sb[t + 64];
    __syncthreads();
    if (t < 32) {
        int x = sb[t] + sb[t + 32];
        #pragma unroll
        for (int o = 16; o > 0; o >>= 1) x += __shfl_xor_sync(0xffffffffu, x, o);
        if (t == 0) sb[0] = x;
    }
    __syncthreads();
    int offset = sb[0];

    if (idx < Nn) {
        g_rowptr[idx] = (incl - v) + offset;
        g_deg[idx] = 0;
    }
    if (idx == 0) g_rowptr[Nn] = Ee;
}

// atomic-free scatter: position = rowptr[dst] + rank[e]
__global__ void k_scatter(const int* __restrict__ edge_index) {
    int e = blockIdx.x * blockDim.x + threadIdx.x;
    if (e < Ee) {
        int d = edge_index[Ee + e];
        int p = g_rowptr[d] + g_rank[e];
        g_col[p] = edge_index[e];
    }
}

// ---------------- AGNN layer: warp per dst node, quarter-warp per edge -----
// R10 math; rows of the main loop prefetched via cp.async double buffer in
// shared memory (no register growth), cols prefetched 2 stages deep.
__global__ void __launch_bounds__(256, 4)
k_agnn(int inA, int last) {
    __shared__ __align__(16) char sbuf[8 * 4096];  // per-warp 4KB (2 bufs x 4 q x 2 rows x 256B)
    int gt = blockIdx.x * blockDim.x + threadIdx.x;
    int node = gt >> 5;
    int lane = threadIdx.x & 31;
    if (node >= Nn) return;

    const float4* __restrict__ xn_in = (const float4*)(inA ? g_xnA : g_xnB);
    const char*  xb = (const char*)xn_in;
    const float* __restrict__ nrm_in = inA ? g_nrmA : g_nrmB;
    float* __restrict__ xn_out  = inA ? (float*)g_xnB : (float*)g_xnA;
    float* __restrict__ nrm_out = inA ? g_nrmB : g_nrmA;

    int wid = threadIdx.x >> 5;
    int q = lane >> 3;                 // quarter id
    int c = lane & 7;                  // dims c*8 .. c*8+7
    int co = c * 2;                    // float4 index within row
    int cb = c * 32;                   // byte offset within row
    unsigned qm = 0xffu << (q * 8);

    // smem slot for this (warp, quarter, lane-chunk); buf p at +p*2048, row r at +r*256
    unsigned sq = (unsigned)__cvta_generic_to_shared(sbuf) + wid * 4096 + q * 512 + cb;

    float4 xd0 = xn_in[node * 16 + co];
    float4 xd1 = xn_in[node * 16 + co + 1];
    float nd = nrm_in[node];

    float s = 0.f;
    float4 a0 = make_float4(0.f, 0.f, 0.f, 0.f);
    float4 a1 = make_float4(0.f, 0.f, 0.f, 0.f);

    // self loop: ||xn||^2 = (nrm/max(nrm,eps))^2
    if (q == 0) {
        float rr = nd / fmaxf(nd, 1e-12f);
        float w = __expf(rr * rr);
        float cs = w * nd;
        s = w;
        a0.x = cs * xd0.x; a0.y = cs * xd0.y; a0.z = cs * xd0.z; a0.w = cs * xd0.w;
        a1.x = cs * xd1.x; a1.y = cs * xd1.y; a1.z = cs * xd1.z; a1.w = cs * xd1.w;
    }

    int beg = g_rowptr[node];
    int nE  = g_rowptr[node + 1] - beg;
    int it = q;

    int c0 = 0, c1 = 0, nc0 = 0, nc1 = 0;
    if (it + 4 < nE) {
        c0 = g_col[beg + it];
        c1 = g_col[beg + it + 4];
        const char* gp0 = xb + (long)c0 * 256 + cb;
        const char* gp1 = xb + (long)c1 * 256 + cb;
        cp16(sq,            gp0);
        cp16(sq + 16,       gp0 + 16);
        cp16(sq + 256,      gp1);
        cp16(sq + 256 + 16, gp1 + 16);
    }
    CP_COMMIT();
    if (it + 12 < nE) { nc0 = g_col[beg + it + 8]; nc1 = g_col[beg + it + 12]; }

    int p = 0;
    while (it + 4 < nE) {
        // prefetch next iteration's rows into buf p^1
        if (it + 12 < nE) {
            unsigned dq = sq + ((unsigned)(p ^ 1) << 11);
            const char* gp0 = xb + (long)nc0 * 256 + cb;
            const char* gp1 = xb + (long)nc1 * 256 + cb;
            cp16(dq,            gp0);
            cp16(dq + 16,       gp0 + 16);
            cp16(dq + 256,      gp1);
            cp16(dq + 256 + 16, gp1 + 16);
        }
        CP_COMMIT();
        float n0 = nrm_in[c0];
        float n1 = nrm_in[c1];
        int tc0 = 0, tc1 = 0;
        if (it + 20 < nE) { tc0 = g_col[beg + it + 16]; tc1 = g_col[beg + it + 20]; }
        CP_WAIT1();
        unsigned rq = sq + ((unsigned)p << 11);
        float4 p0 = lds128(rq);
        float4 p1 = lds128(rq + 16);
        float4 r0 = lds128(rq + 256);
        float4 r1 = lds128(rq + 256 + 16);
        float d0 = red8(dot8(xd0, xd1, p0, p1), qm);
        float d1 = red8(dot8(xd0, xd1, r0, r1), qm);
        float w0 = __expf(d0);
        float w1 = __expf(d1);
        s += w0 + w1;
        float cs0 = w0 * n0, cs1 = w1 * n1;
        a0.x += cs0 * p0.x + cs1 * r0.x;
        a0.y += cs0 * p0.y + cs1 * r0.y;
        a0.z += cs0 * p0.z + cs1 * r0.z;
        a0.w += cs0 * p0.w + cs1 * r0.w;
        a1.x += cs0 * p1.x + cs1 * r1.x;
        a1.y += cs0 * p1.y + cs1 * r1.y;
        a1.z += cs0 * p1.z + cs1 * r1.z;
        a1.w += cs0 * p1.w + cs1 * r1.w;
        c0 = nc0; c1 = nc1; nc0 = tc0; nc1 = tc1;
        p ^= 1;
        it += 8;
    }
    CP_WAIT0();
    // remainder: 1 edge per quarter per iteration (direct LDG)
    for (; it < nE; it += 4) {
        int s0 = g_col[beg + it];
        float4 p0 = xn_in[s0 * 16 + co];
        float4 p1 = xn_in[s0 * 16 + co + 1];
        float n0 = nrm_in[s0];
        float d0 = red8(dot8(xd0, xd1, p0, p1), qm);
        float w0 = __expf(d0);
        s += w0;
        float cs0 = w0 * n0;
        a0.x += cs0 * p0.x; a0.y += cs0 * p0.y; a0.z += cs0 * p0.z; a0.w += cs0 * p0.w;
        a1.x += cs0 * p1.x; a1.y += cs0 * p1.y; a1.z += cs0 * p1.z; a1.w += cs0 * p1.w;
    }
    __syncwarp();

    // combine the 4 quarters (each quarter holds the same 64 dims)
    #pragma unroll
    for (int o = 8; o <= 16; o <<= 1) {
        s    += __shfl_xor_sync(0xffffffffu, s,    o);
        a0.x += __shfl_xor_sync(0xffffffffu, a0.x, o);
        a0.y += __shfl_xor_sync(0xffffffffu, a0.y, o);
        a0.z += __shfl_xor_sync(0xffffffffu, a0.z, o);
        a0.w += __shfl_xor_sync(0xffffffffu, a0.w, o);
        a1.x += __shfl_xor_sync(0xffffffffu, a1.x, o);
        a1.y += __shfl_xor_sync(0xffffffffu, a1.y, o);
        a1.z += __shfl_xor_sync(0xffffffffu, a1.z, o);
        a1.w += __shfl_xor_sync(0xffffffffu, a1.w, o);
    }

    float invs = 1.f / s;
    float4 o0, o1;
    o0.x = a0.x * invs; o0.y = a0.y * invs; o0.z = a0.z * invs; o0.w = a0.w * invs;
    o1.x = a1.x * invs; o1.y = a1.y * invs; o1.z = a1.z * invs; o1.w = a1.w * invs;

    if (last) {
        if (q == 0) {
            *(float4*)&g_bufA[node * Hh + c * 8]     = o0;
            *(float4*)&g_bufA[node * Hh + c * 8 + 4] = o1;
        }
    } else {
        float ss = red8(dot8(o0, o1, o0, o1), qm);
        float nrm = sqrtf(ss);
        float inv = 1.f / fmaxf(nrm, 1e-12f);
        if (q == 0) {
            float4 x0, x1;
            x0.x = o0.x * inv; x0.y = o0.y * inv; x0.z = o0.z * inv; x0.w = o0.w * inv;
            x1.x = o1.x * inv; x1.y = o1.y * inv; x1.z = o1.z * inv; x1.w = o1.w * inv;
            *(float4*)(xn_out + node * Hh + c * 8)     = x0;
            *(float4*)(xn_out + node * Hh + c * 8 + 4) = x1;
            if (c == 0) nrm_out[node] = nrm;
        }
    }
}

// ---------------- GEMM2 + log_softmax, 32 rows/block (4 rows per warp) -----
__global__ void k_gemm2_lsm(const float* __restrict__ W2, const float* __restrict__ b2,
                            float* __restrict__ out) {
    __shared__ float W2s[Hh * Cc + 32];
    __shared__ float b2s[64];
    __shared__ float Hs[32][Hh];
    int t = threadIdx.x;
    int row0 = blockIdx.x * 32;
    for (int i = t; i < Hh * Cc; i += 256) W2s[i] = W2[i];
    if (t < 64) b2s[t] = (t < Cc) ? b2[t] : 0.f;
    for (int i = t; i < 32 * Hh; i += 256) {
        int r = i >> 6, k = i & 63;
        int grow = row0 + r;
        Hs[r][k] = (grow < Nn) ? g_bufA[grow * Hh + k] : 0.f;
    }
    __syncthreads();

    int wrp = t >> 5;
    int l = t & 31;

    #pragma unroll
    for (int rr = 0; rr < 4; rr++) {
        int rl = wrp * 4 + rr;
        int row = row0 + rl;
        if (row >= Nn) break;

        float a0 = 0.f, a1 = 0.f;
        #pragma unroll 8
        for (int k = 0; k < Hh; k++) {
            float hk = Hs[rl][k];
            a0 += hk * W2s[k * Cc + l];
            a1 += hk * W2s[k * Cc + 32 + l];
        }
        float v0 = a0 + b2s[l];
        float v1 = a1 + b2s[32 + l];

        float m = v0;
        if (l < 8) m = fmaxf(m, v1);
        m = warp_max(m);
        float e = __expf(v0 - m) + ((l < 8) ? __expf(v1 - m) : 0.f);
        float se = warp_sum(e);
        float ls = m + logf(se);
        out[row * Cc + l] = v0 - ls;
        if (l < 8) out[row * Cc + 32 + l] = v1 - ls;
    }
}

// ---------------- launch ----------------------------------------------------
extern "C" void kernel_launch(void* const* d_in, const int* in_sizes, int n_in,
                              void* d_out, int out_size) {
    const float* x   = (const float*)d_in[0];
    const float* W1  = (const float*)d_in[1];
    const float* b1  = (const float*)d_in[2];
    const float* W2  = (const float*)d_in[3];
    const float* b2  = (const float*)d_in[4];
    const int* eidx  = (const int*)d_in[5];
    float* out = (float*)d_out;

    k_gemm1_hist<<<NB_G1 + NB_HIST, 256>>>(x, W1, b1, eidx);
    k_scan<<<NB_SCAN, 1024>>>();                       // rowptr, zeroes deg
    k_scatter<<<(Ee + 255) / 256, 256>>>(eidx);        // col (no atomics)

    // 4 AGNN layers, xn ping-pong A->B->A->B, last writes h -> bufA
    int inA = 1;
    for (int layer = 0; layer < 4; layer++) {
        k_agnn<<<(Nn * 32 + 255) / 256, 256>>>(inA, layer == 3);
        inA ^= 1;
    }

    // out = log_softmax(h@W2+b2)
    k_gemm2_lsm<<<(Nn + 31) / 32, 256>>>(W2, b2, out);
}

// round 13
// speedup vs baseline: 1.1650x; 1.1650x over previous
#include <cuda_runtime.h>
#include <math.h>

#define Nn   100000
#define Ee   1600000
#define Fin  128
#define Hh   64
#define Cc   40
#define NB_SCAN ((Nn + 1023) / 1024)
#define NB_G1  ((Nn + 255) / 256)       // gemm1 blocks in the fused kernel
#define NB_HIST ((Ee + 255) / 256)      // hist blocks in the fused kernel
#define FLAGBIT (1 << 30)

// ---------------- scratch (static device globals; no runtime alloc) -------
__device__ __align__(256) float g_bufA[Nn * Hh];     // final h for gemm2
__device__ __align__(256) float g_xnA [Nn * Hh];
__device__ __align__(256) float g_xnB [Nn * Hh];
__device__ float g_nrmA[Nn];
__device__ float g_nrmB[Nn];
__device__ int   g_deg [Nn];          // zero at module load; re-zeroed each call by k_scan
__device__ int   g_rowptr[Nn + 1];
__device__ int   g_rank[Ee];
__device__ int   g_col [Ee];
__device__ int   g_bsums[NB_SCAN];

// ---------------- helpers --------------------------------------------------
__device__ __forceinline__ float warp_sum(float v) {
    #pragma unroll
    for (int o = 16; o > 0; o >>= 1) v += __shfl_xor_sync(0xffffffffu, v, o);
    return v;
}
__device__ __forceinline__ float warp_max(float v) {
    #pragma unroll
    for (int o = 16; o > 0; o >>= 1) v = fmaxf(v, __shfl_xor_sync(0xffffffffu, v, o));
    return v;
}
__device__ __forceinline__ float red8(float v, unsigned m) {
    v += __shfl_xor_sync(m, v, 1);
    v += __shfl_xor_sync(m, v, 2);
    v += __shfl_xor_sync(m, v, 4);
    return v;
}
__device__ __forceinline__ float dot8(float4 a0, float4 a1, float4 b0, float4 b1) {
    return a0.x * b0.x + a0.y * b0.y + a0.z * b0.z + a0.w * b0.w
         + a1.x * b1.x + a1.y * b1.y + a1.z * b1.z + a1.w * b1.w;
}

#define FFMA2(d, a, b, c) \
    asm("fma.rn.f32x2 %0, %1, %2, %3;" : "=l"(d) : "l"(a), "l"(b), "l"(c))

union F2U { float2 f; unsigned long long u; };
__device__ __forceinline__ unsigned long long pack_dup(float v) {
    unsigned long long r;
    asm("mov.b64 %0, {%1, %1};" : "=l"(r) : "f"(v));
    return r;
}

// ---------------- fused GEMM1 + hist ---------------------------------------
__global__ void __launch_bounds__(256, 2)
k_gemm1_hist(const float* __restrict__ x, const float* __restrict__ W1,
             const float* __restrict__ b1, const int* __restrict__ edge_index) {
    __shared__ __align__(16) float Ws[Fin * Hh];   // 32 KB
    __shared__ __align__(16) float As[16][260];    // 16.25 KB, padded stride
    int t = threadIdx.x;                  // 256 threads

    if (blockIdx.x >= NB_G1) {
        // ---- hist part ----
        int bb = blockIdx.x - NB_G1;
        if (bb == 0 && t < NB_SCAN) g_bsums[t] = 0;
        int e = bb * 256 + t;
        if (e < Ee) {
            int r = atomicAdd(&g_deg[edge_index[Ee + e]], 1);
            g_rank[e] = r;
        }
        return;
    }

    // ---- gemm1 part ----
    int row0 = blockIdx.x * 256;
    for (int i = t; i < Fin * Hh; i += 256) Ws[i] = W1[i];

    int tx = t & 7;    // col groups tx*4 and 32+tx*4
    int ty = t >> 3;   // row groups ty*4 and 128+ty*4
    unsigned long long acc[8][4] = {};    // [row][colpair], 64 regs

    for (int k0 = 0; k0 < Fin; k0 += 16) {
        __syncthreads();
        {
            int c = t & 15;
            int r0 = t >> 4;
            #pragma unroll
            for (int i = 0; i < 16; i++) {
                int rr = r0 + i * 16;
                int grow = row0 + rr;
                As[c][rr] = (grow < Nn) ? x[grow * Fin + k0 + c] : 0.f;
            }
        }
        __syncthreads();
        #pragma unroll
        for (int kk = 0; kk < 16; kk++) {
            float4 af0 = *(const float4*)&As[kk][ty * 4];
            float4 af1 = *(const float4*)&As[kk][128 + ty * 4];
            ulonglong2 w0 = *(const ulonglong2*)&Ws[(k0 + kk) * Hh + tx * 4];
            ulonglong2 w1 = *(const ulonglong2*)&Ws[(k0 + kk) * Hh + 32 + tx * 4];
            unsigned long long ad[8];
            ad[0] = pack_dup(af0.x); ad[1] = pack_dup(af0.y);
            ad[2] = pack_dup(af0.z); ad[3] = pack_dup(af0.w);
            ad[4] = pack_dup(af1.x); ad[5] = pack_dup(af1.y);
            ad[6] = pack_dup(af1.z); ad[7] = pack_dup(af1.w);
            #pragma unroll
            for (int r = 0; r < 8; r++) {
                FFMA2(acc[r][0], ad[r], w0.x, acc[r][0]);
                FFMA2(acc[r][1], ad[r], w0.y, acc[r][1]);
                FFMA2(acc[r][2], ad[r], w1.x, acc[r][2]);
                FFMA2(acc[r][3], ad[r], w1.y, acc[r][3]);
            }
        }
    }

    float4 bb0 = *(const float4*)&b1[tx * 4];
    float4 bb1 = *(const float4*)&b1[32 + tx * 4];
    unsigned qm = 0xffu << (t & 24);
    #pragma unroll
    for (int r = 0; r < 8; r++) {
        int grow = row0 + ((r < 4) ? (ty * 4 + r) : (128 + ty * 4 + r - 4));
        F2U u0, u1, u2, u3;
        u0.u = acc[r][0]; u1.u = acc[r][1]; u2.u = acc[r][2]; u3.u = acc[r][3];
        float4 o0, o1;
        o0.x = fmaxf(u0.f.x + bb0.x, 0.f);
        o0.y = fmaxf(u0.f.y + bb0.y, 0.f);
        o0.z = fmaxf(u1.f.x + bb0.z, 0.f);
        o0.w = fmaxf(u1.f.y + bb0.w, 0.f);
        o1.x = fmaxf(u2.f.x + bb1.x, 0.f);
        o1.y = fmaxf(u2.f.y + bb1.y, 0.f);
        o1.z = fmaxf(u3.f.x + bb1.z, 0.f);
        o1.w = fmaxf(u3.f.y + bb1.w, 0.f);
        float ss = red8(dot8(o0, o1, o0, o1), qm);
        float nrm = sqrtf(ss);
        float inv = 1.f / fmaxf(nrm, 1e-12f);
        if (grow < Nn) {
            float4 x0, x1;
            x0.x = o0.x * inv; x0.y = o0.y * inv; x0.z = o0.z * inv; x0.w = o0.w * inv;
            x1.x = o1.x * inv; x1.y = o1.y * inv; x1.z = o1.z * inv; x1.w = o1.w * inv;
            *(float4*)&g_xnA[grow * Hh + tx * 4]      = x0;
            *(float4*)&g_xnA[grow * Hh + 32 + tx * 4] = x1;
            if (tx == 0) g_nrmA[grow] = nrm;
        }
    }
}

// ---------------- single-kernel scan (decoupled lookback) ------------------
__global__ void k_scan() {
    __shared__ int s[1024];
    __shared__ int sb[128];
    int t = threadIdx.x;
    int b = blockIdx.x;
    int idx = b * 1024 + t;
    int v = (idx < Nn) ? g_deg[idx] : 0;
    s[t] = v;
    __syncthreads();
    #pragma unroll
    for (int off = 1; off < 1024; off <<= 1) {
        int x = (t >= off) ? s[t - off] : 0;
        __syncthreads();
        s[t] += x;
        __syncthreads();
    }
    int incl = s[t];
    if (t == 1023) atomicExch(&g_bsums[b], incl | FLAGBIT);

    int myv = 0;
    if (t < b) {
        int x;
        do { x = atomicAdd(&g_bsums[t], 0); } while (!(x & FLAGBIT));
        myv = x & (FLAGBIT - 1);
    }
    if (t < 128) sb[t] = (t < b) ? myv : 0;
    __syncthreads();
    if (t < 64) sb[t] += sb[t + 64];
    __syncthreads();
    if (t < 32) {
        int x = sb[t] + sb[t + 32];
        #pragma unroll
        for (int o = 16; o > 0; o >>= 1) x += __shfl_xor_sync(0xffffffffu, x, o);
        if (t == 0) sb[0] = x;
    }
    __syncthreads();
    int offset = sb[0];

    if (idx < Nn) {
        g_rowptr[idx] = (incl - v) + offset;
        g_deg[idx] = 0;
    }
    if (idx == 0) g_rowptr[Nn] = Ee;
}

// atomic-free scatter: position = rowptr[dst] + rank[e]
__global__ void k_scatter(const int* __restrict__ edge_index) {
    int e = blockIdx.x * blockDim.x + threadIdx.x;
    if (e < Ee) {
        int d = edge_index[Ee + e];
        int p = g_rowptr[d] + g_rank[e];
        g_col[p] = edge_index[e];
    }
}

// ---------------- AGNN layer: warp per dst node, quarter-warp per edge -----
// single-edge loop (minimal registers -> higher occupancy), col prefetch 1 deep
__global__ void __launch_bounds__(256, 5)
k_agnn(int inA, int last) {
    int gt = blockIdx.x * blockDim.x + threadIdx.x;
    int node = gt >> 5;
    int lane = threadIdx.x & 31;
    if (node >= Nn) return;

    const float4* __restrict__ xn_in = (const float4*)(inA ? g_xnA : g_xnB);
    const float*  __restrict__ nrm_in = inA ? g_nrmA : g_nrmB;
    float* __restrict__ xn_out  = inA ? (float*)g_xnB : (float*)g_xnA;
    float* __restrict__ nrm_out = inA ? g_nrmB : g_nrmA;

    int q = lane >> 3;                 // quarter id
    int c = lane & 7;                  // dims c*8 .. c*8+7
    int co = c * 2;
    unsigned qm = 0xffu << (q * 8);

    float4 xd0 = xn_in[node * 16 + co];
    float4 xd1 = xn_in[node * 16 + co + 1];
    float nd = nrm_in[node];

    float s = 0.f;
    float4 a0 = make_float4(0.f, 0.f, 0.f, 0.f);
    float4 a1 = make_float4(0.f, 0.f, 0.f, 0.f);

    // self loop: ||xn||^2 = (nrm/max(nrm,eps))^2
    if (q == 0) {
        float rr = nd / fmaxf(nd, 1e-12f);
        float w = __expf(rr * rr);
        float cs = w * nd;
        s = w;
        a0.x = cs * xd0.x; a0.y = cs * xd0.y; a0.z = cs * xd0.z; a0.w = cs * xd0.w;
        a1.x = cs * xd1.x; a1.y = cs * xd1.y; a1.z = cs * xd1.z; a1.w = cs * xd1.w;
    }

    int beg = g_rowptr[node];
    int nE  = g_rowptr[node + 1] - beg;
    int it = q;
    int nc = (it < nE) ? g_col[beg + it] : 0;
    while (it < nE) {
        int s0 = nc;
        int itn = it + 4;
        if (itn < nE) nc = g_col[beg + itn];
        float4 p0 = xn_in[s0 * 16 + co];
        float4 p1 = xn_in[s0 * 16 + co + 1];
        float n0 = nrm_in[s0];
        float d0 = red8(dot8(xd0, xd1, p0, p1), qm);
        float w0 = __expf(d0);
        s += w0;
        float cs0 = w0 * n0;
        a0.x += cs0 * p0.x; a0.y += cs0 * p0.y; a0.z += cs0 * p0.z; a0.w += cs0 * p0.w;
        a1.x += cs0 * p1.x; a1.y += cs0 * p1.y; a1.z += cs0 * p1.z; a1.w += cs0 * p1.w;
        it = itn;
    }
    __syncwarp();

    // combine the 4 quarters (each quarter holds the same 64 dims)
    #pragma unroll
    for (int o = 8; o <= 16; o <<= 1) {
        s    += __shfl_xor_sync(0xffffffffu, s,    o);
        a0.x += __shfl_xor_sync(0xffffffffu, a0.x, o);
        a0.y += __shfl_xor_sync(0xffffffffu, a0.y, o);
        a0.z += __shfl_xor_sync(0xffffffffu, a0.z, o);
        a0.w += __shfl_xor_sync(0xffffffffu, a0.w, o);
        a1.x += __shfl_xor_sync(0xffffffffu, a1.x, o);
        a1.y += __shfl_xor_sync(0xffffffffu, a1.y, o);
        a1.z += __shfl_xor_sync(0xffffffffu, a1.z, o);
        a1.w += __shfl_xor_sync(0xffffffffu, a1.w, o);
    }

    float invs = 1.f / s;
    float4 o0, o1;
    o0.x = a0.x * invs; o0.y = a0.y * invs; o0.z = a0.z * invs; o0.w = a0.w * invs;
    o1.x = a1.x * invs; o1.y = a1.y * invs; o1.z = a1.z * invs; o1.w = a1.w * invs;

    if (last) {
        if (q == 0) {
            *(float4*)&g_bufA[node * Hh + c * 8]     = o0;
            *(float4*)&g_bufA[node * Hh + c * 8 + 4] = o1;
        }
    } else {
        // fused normalize of the output row
        float ss = red8(dot8(o0, o1, o0, o1), qm);
        float nrm = sqrtf(ss);
        float inv = 1.f / fmaxf(nrm, 1e-12f);
        if (q == 0) {
            float4 x0, x1;
            x0.x = o0.x * inv; x0.y = o0.y * inv; x0.z = o0.z * inv; x0.w = o0.w * inv;
            x1.x = o1.x * inv; x1.y = o1.y * inv; x1.z = o1.z * inv; x1.w = o1.w * inv;
            *(float4*)(xn_out + node * Hh + c * 8)     = x0;
            *(float4*)(xn_out + node * Hh + c * 8 + 4) = x1;
            if (c == 0) nrm_out[node] = nrm;
        }
    }
}

// ---------------- GEMM2 + log_softmax, 32 rows/block (4 rows per warp) -----
__global__ void k_gemm2_lsm(const float* __restrict__ W2, const float* __restrict__ b2,
                            float* __restrict__ out) {
    __shared__ float W2s[Hh * Cc + 32];
    __shared__ float b2s[64];
    __shared__ float Hs[32][Hh];
    int t = threadIdx.x;
    int row0 = blockIdx.x * 32;
    for (int i = t; i < Hh * Cc; i += 256) W2s[i] = W2[i];
    if (t < 64) b2s[t] = (t < Cc) ? b2[t] : 0.f;
    for (int i = t; i < 32 * Hh; i += 256) {
        int r = i >> 6, k = i & 63;
        int grow = row0 + r;
        Hs[r][k] = (grow < Nn) ? g_bufA[grow * Hh + k] : 0.f;
    }
    __syncthreads();

    int wrp = t >> 5;
    int l = t & 31;

    #pragma unroll
    for (int rr = 0; rr < 4; rr++) {
        int rl = wrp * 4 + rr;
        int row = row0 + rl;
        if (row >= Nn) break;

        float a0 = 0.f, a1 = 0.f;
        #pragma unroll 8
        for (int k = 0; k < Hh; k++) {
            float hk = Hs[rl][k];
            a0 += hk * W2s[k * Cc + l];
            a1 += hk * W2s[k * Cc + 32 + l];
        }
        float v0 = a0 + b2s[l];
        float v1 = a1 + b2s[32 + l];

        float m = v0;
        if (l < 8) m = fmaxf(m, v1);
        m = warp_max(m);
        float e = __expf(v0 - m) + ((l < 8) ? __expf(v1 - m) : 0.f);
        float se = warp_sum(e);
        float ls = m + logf(se);
        out[row * Cc + l] = v0 - ls;
        if (l < 8) out[row * Cc + 32 + l] = v1 - ls;
    }
}

// ---------------- launch ----------------------------------------------------
extern "C" void kernel_launch(void* const* d_in, const int* in_sizes, int n_in,
                              void* d_out, int out_size) {
    const float* x   = (const float*)d_in[0];
    const float* W1  = (const float*)d_in[1];
    const float* b1  = (const float*)d_in[2];
    const float* W2  = (const float*)d_in[3];
    const float* b2  = (const float*)d_in[4];
    const int* eidx  = (const int*)d_in[5];
    float* out = (float*)d_out;

    k_gemm1_hist<<<NB_G1 + NB_HIST, 256>>>(x, W1, b1, eidx);
    k_scan<<<NB_SCAN, 1024>>>();                       // rowptr, zeroes deg
    k_scatter<<<(Ee + 255) / 256, 256>>>(eidx);        // col (no atomics)

    // 4 AGNN layers, xn ping-pong A->B->A->B, last writes h -> bufA
    int inA = 1;
    for (int layer = 0; layer < 4; layer++) {
        k_agnn<<<(Nn * 32 + 255) / 256, 256>>>(inA, layer == 3);
        inA ^= 1;
    }

    // out = log_softmax(h@W2+b2)
    k_gemm2_lsm<<<(Nn + 31) / 32, 256>>>(W2, b2, out);
}